// round 17
// baseline (speedup 1.0000x reference)
#include <cuda_runtime.h>
#include <cuda_fp16.h>
#include <math.h>
#include <stdint.h>

#define Bb    2
#define Ss    2048
#define Dd    2048
#define Hh    32
#define KVHh  8
#define HDd   64
#define QKVN  3072
#define Mrows (Bb*Ss)
#define OUTOFF ((size_t)Bb*Ss*Dd)
#define ATT_SCALE 0.125f

// ---------------- scratch ----------------------------------------------------
__device__ __half g_x[(size_t)Mrows*Dd];
__device__ __half g_q[(size_t)Bb*Hh*Ss*HDd];
__device__ __half g_k[(size_t)Bb*KVHh*Ss*HDd];
__device__ __half g_v[(size_t)Bb*KVHh*Ss*HDd];
__device__ __half g_attn[(size_t)Mrows*Dd];
__device__ __half g_wqkvh[(size_t)Dd*QKVN];
__device__ __half g_wouth[(size_t)Dd*Dd];
__device__ float g_cos[(size_t)Bb*Ss*32];
__device__ float g_sin[(size_t)Bb*Ss*32];

__device__ __forceinline__ uint32_t pkh2(float x, float y) {
    __half2 h = __floats2half2_rn(x, y);
    return *(uint32_t*)&h;
}
__device__ __forceinline__ void mma_f16(float c[4], uint32_t a0, uint32_t a1,
                                        uint32_t a2, uint32_t a3,
                                        uint32_t b0, uint32_t b1)
{
    asm volatile(
        "mma.sync.aligned.m16n8k16.row.col.f32.f16.f16.f32 "
        "{%0,%1,%2,%3}, {%4,%5,%6,%7}, {%8,%9}, {%0,%1,%2,%3};"
        : "+f"(c[0]), "+f"(c[1]), "+f"(c[2]), "+f"(c[3])
        : "r"(a0), "r"(a1), "r"(a2), "r"(a3), "r"(b0), "r"(b1));
}
__device__ __forceinline__ void ldsm4(uint32_t& r0, uint32_t& r1,
                                      uint32_t& r2, uint32_t& r3, uint32_t saddr)
{
    asm volatile(
        "ldmatrix.sync.aligned.m8n8.x4.shared.b16 {%0,%1,%2,%3}, [%4];"
        : "=r"(r0), "=r"(r1), "=r"(r2), "=r"(r3) : "r"(saddr));
}
__device__ __forceinline__ void ldsm4t(uint32_t& r0, uint32_t& r1,
                                       uint32_t& r2, uint32_t& r3, uint32_t saddr)
{
    asm volatile(
        "ldmatrix.sync.aligned.m8n8.x4.trans.shared.b16 {%0,%1,%2,%3}, [%4];"
        : "=r"(r0), "=r"(r1), "=r"(r2), "=r"(r3) : "r"(saddr));
}
__device__ __forceinline__ void cpa16(uint32_t smem_addr, const void* gptr) {
    asm volatile("cp.async.cg.shared.global [%0], [%1], 16;"
                 :: "r"(smem_addr), "l"(gptr));
}
__device__ __forceinline__ void cpa4(uint32_t smem_addr, const void* gptr) {
    asm volatile("cp.async.ca.shared.global [%0], [%1], 4;"
                 :: "r"(smem_addr), "l"(gptr));
}
__device__ __forceinline__ void cpa_commit() {
    asm volatile("cp.async.commit_group;");
}
template<int N>
__device__ __forceinline__ void cpa_wait() {
    asm volatile("cp.async.wait_group %0;" :: "n"(N));
}
__device__ __forceinline__ float clip8(float v) {
    return fminf(fmaxf(v, -8.f), 8.f);
}

// ---------------- fused prep: LN1 + rope table + weight cvt -------------------
#define NCVT ((Dd*QKVN/4 + Dd*Dd/4) / 256)
__global__ __launch_bounds__(256) void prep_kernel(
    const float* __restrict__ hs, const float* __restrict__ ln1,
    const int* __restrict__ pid,
    const float* __restrict__ wqkv, const float* __restrict__ wout)
{
    int bid = blockIdx.x;
    if (bid < Mrows) {
        int row = bid;
        const float4* x4 = (const float4*)(hs + (size_t)row * Dd);
        float s = 0.f, s2 = 0.f;
        float4 v[2];
        #pragma unroll
        for (int i = 0; i < 2; i++) {
            v[i] = x4[threadIdx.x + i * 256];
            s  += v[i].x + v[i].y + v[i].z + v[i].w;
            s2 += v[i].x*v[i].x + v[i].y*v[i].y + v[i].z*v[i].z + v[i].w*v[i].w;
        }
        #pragma unroll
        for (int o = 16; o; o >>= 1) {
            s  += __shfl_xor_sync(0xffffffffu, s,  o);
            s2 += __shfl_xor_sync(0xffffffffu, s2, o);
        }
        __shared__ float ws[8], ws2[8];
        int w = threadIdx.x >> 5, l = threadIdx.x & 31;
        if (l == 0) { ws[w] = s; ws2[w] = s2; }
        __syncthreads();
        if (threadIdx.x < 32) {
            s  = (l < 8) ? ws[l]  : 0.f;
            s2 = (l < 8) ? ws2[l] : 0.f;
            #pragma unroll
            for (int o = 4; o; o >>= 1) {
                s  += __shfl_xor_sync(0xffffffffu, s,  o);
                s2 += __shfl_xor_sync(0xffffffffu, s2, o);
            }
            if (l == 0) { ws[0] = s; ws2[0] = s2; }
        }
        __syncthreads();
        float mean = ws[0] * (1.f / Dd);
        float var  = ws2[0] * (1.f / Dd) - mean * mean;
        float inv  = rsqrtf(var + 1e-6f);
        __half* o_ = g_x + (size_t)row * Dd;
        #pragma unroll
        for (int i = 0; i < 2; i++) {
            int c = (threadIdx.x + i * 256) * 4;
            const float4 sv = *(const float4*)(ln1 + c);
            uint32_t p0 = pkh2((v[i].x - mean) * inv * sv.x,
                               (v[i].y - mean) * inv * sv.y);
            uint32_t p1 = pkh2((v[i].z - mean) * inv * sv.z,
                               (v[i].w - mean) * inv * sv.w);
            uint2 pk; pk.x = p0; pk.y = p1;
            *(uint2*)(o_ + c) = pk;
        }
    } else if (bid < Mrows + 512) {
        __shared__ double sInv[32];
        if (threadIdx.x < 32) {
            int i = threadIdx.x;
            sInv[i] = exp(-((double)(2 * i) / 64.0) * log(500000.0));
        }
        __syncthreads();
        int idx = (bid - Mrows) * 256 + threadIdx.x;
        int i = idx & 31;
        int s = (idx >> 5) & (Ss - 1);
        int b = idx >> 16;
        double pos = (double)pid[b * Ss + s];
        double ang = pos * sInv[i];
        double k = rint(ang * 0.15915494309189535);
        float r = (float)(ang - k * 6.283185307179586);
        g_cos[idx] = cosf(r);
        g_sin[idx] = sinf(r);
    } else {
        int i = (bid - Mrows - 512) * 256 + threadIdx.x;
        int n1 = Dd * QKVN / 4;
        const float* src; __half* dst;
        if (i < n1) { src = wqkv + (size_t)i * 4; dst = g_wqkvh + (size_t)i * 4; }
        else {
            i -= n1;
            src = wout + (size_t)i * 4; dst = g_wouth + (size_t)i * 4;
        }
        float4 v = *(const float4*)src;
        uint32_t* d = (uint32_t*)dst;
        d[0] = pkh2(v.x, v.y);
        d[1] = pkh2(v.z, v.w);
    }
}

// ---------------- LayerNorm (fp32 out; LN2) ------------------------------------
__global__ __launch_bounds__(256) void ln_kernel(
    const float* __restrict__ in, const float* __restrict__ sc,
    float* __restrict__ outp)
{
    int row = blockIdx.x;
    const float4* x4 = (const float4*)(in + (size_t)row * Dd);
    float s = 0.f, s2 = 0.f;
    float4 v[2];
    #pragma unroll
    for (int i = 0; i < 2; i++) {
        v[i] = x4[threadIdx.x + i * 256];
        s  += v[i].x + v[i].y + v[i].z + v[i].w;
        s2 += v[i].x*v[i].x + v[i].y*v[i].y + v[i].z*v[i].z + v[i].w*v[i].w;
    }
    #pragma unroll
    for (int o = 16; o; o >>= 1) {
        s  += __shfl_xor_sync(0xffffffffu, s,  o);
        s2 += __shfl_xor_sync(0xffffffffu, s2, o);
    }
    __shared__ float ws[8], ws2[8];
    int w = threadIdx.x >> 5, l = threadIdx.x & 31;
    if (l == 0) { ws[w] = s; ws2[w] = s2; }
    __syncthreads();
    if (threadIdx.x < 32) {
        s  = (l < 8) ? ws[l]  : 0.f;
        s2 = (l < 8) ? ws2[l] : 0.f;
        #pragma unroll
        for (int o = 4; o; o >>= 1) {
            s  += __shfl_xor_sync(0xffffffffu, s,  o);
            s2 += __shfl_xor_sync(0xffffffffu, s2, o);
        }
        if (l == 0) { ws[0] = s; ws2[0] = s2; }
    }
    __syncthreads();
    float mean = ws[0] * (1.f / Dd);
    float var  = ws2[0] * (1.f / Dd) - mean * mean;
    float inv  = rsqrtf(var + 1e-6f);
    #pragma unroll
    for (int i = 0; i < 2; i++) {
        int c = (threadIdx.x + i * 256) * 4;
        const float4 sv = *(const float4*)(sc + c);
        float4 ov;
        ov.x = (v[i].x - mean) * inv * sv.x;
        ov.y = (v[i].y - mean) * inv * sv.y;
        ov.z = (v[i].z - mean) * inv * sv.z;
        ov.w = (v[i].w - mean) * inv * sv.w;
        *(float4*)(outp + (size_t)row * Dd + c) = ov;
    }
}

// ---------------- FP16 GEMM 128x128x64, 3-stage cp.async ----------------------
// 1D grid with L2-aware supertile rasterization (4 row-tiles per column group)
#define BM 128
#define BN 128
#define BK 64
#define AS_U 36
#define AS_U32S (BM * AS_U)
#define BS_U32S (BK * 64)
#define STAGE_U (AS_U32S + BS_U32S)
#define NSTG 3

__global__ __launch_bounds__(256, 2) void gemm_f16_kernel(
    const __half* __restrict__ A, const __half* __restrict__ Bw,
    void* __restrict__ Cp, int M, int N, int K, int mode,
    const float* __restrict__ resid)
{
    extern __shared__ uint32_t smu[];
    // supertile rasterization: groups of 4 row-tiles sweep columns together
    int nTilesM = M / BM;                    // 32
    int bid = blockIdx.x;
    int grpRows = 4;
    int tilesPerGrp = grpRows * (N / BN);
    int grp = bid / tilesPerGrp;
    int rem = bid % tilesPerGrp;
    int by = grp * grpRows + (rem % grpRows);
    int bx = rem / grpRows;
    if (grp == nTilesM / grpRows) { /* unreachable for our sizes */ }
    int row0 = by * BM, col0 = bx * BN;

    int t = threadIdx.x;
    int w = t >> 5, l = t & 31;
    int warpM = w >> 1, warpN = w & 1;
    int lr = l >> 2, lc = l & 3;

    const uint4* Au = (const uint4*)A;
    const uint4* Bu = (const uint4*)Bw;
    int K8 = K >> 3, N8 = N >> 3;

    uint32_t smuBase = (uint32_t)__cvta_generic_to_shared(smu);
    int bC0 = (col0 >> 3);

    float acc[2][8][4];
    #pragma unroll
    for (int mf = 0; mf < 2; mf++)
        #pragma unroll
        for (int nf = 0; nf < 8; nf++)
            #pragma unroll
            for (int r = 0; r < 4; r++) acc[mf][nf][r] = 0.f;

    int nk = K / BK;
    auto issuePart = [&](int kt, int stg, int i0, int i1) {
        if (kt < nk) {
            int k0 = kt * BK;
            uint32_t aBase = smuBase + stg * STAGE_U * 4;
            uint32_t bBase = aBase + AS_U32S * 4;
            #pragma unroll
            for (int i = 0; i < 4; i++) {
                if (i < i0 || i >= i1) continue;
                int idx = i * 256 + t;
                int ar = idx >> 3, ac = idx & 7;
                cpa16(aBase + (ar * AS_U + ac * 4) * 4,
                      Au + (size_t)(row0 + ar) * K8 + (k0 >> 3) + ac);
                int bk = idx >> 4, bc = idx & 15;
                cpa16(bBase + (bk * 64 + ((bc * 4) ^ ((bk & 7) << 2))) * 4,
                      Bu + (size_t)(k0 + bk) * N8 + bC0 + bc);
            }
        }
    };

    issuePart(0, 0, 0, 4); cpa_commit();
    issuePart(1, 1, 0, 4); cpa_commit();

    int aLdsmRow = l & 15;
    int aLdsmCol = (l >> 4) << 2;

    for (int kt = 0; kt < nk; kt++) {
        cpa_wait<1>();
        __syncthreads();

        uint32_t asAddr = smuBase + (kt % NSTG) * STAGE_U * 4;
        uint32_t bsAddr = asAddr + AS_U32S * 4;
        #pragma unroll
        for (int ks = 0; ks < 4; ks++) {
            if (ks == 1) issuePart(kt + 2, (kt + 2) % NSTG, 0, 2);
            if (ks == 2) { issuePart(kt + 2, (kt + 2) % NSTG, 2, 4); cpa_commit(); }

            uint32_t af[2][4];
            #pragma unroll
            for (int mf = 0; mf < 2; mf++) {
                int r = warpM * 32 + mf * 16;
                ldsm4(af[mf][0], af[mf][1], af[mf][2], af[mf][3],
                      asAddr + ((r + aLdsmRow) * AS_U + ks * 8 + aLdsmCol) * 4);
            }
            #pragma unroll
            for (int nfp = 0; nfp < 4; nfp++) {
                int krow = ks * 16 + (l & 15);
                int col = warpN * 32 + nfp * 8 + ((l >> 4) << 2);
                col ^= (krow & 7) << 2;
                uint32_t b0, b1, b2, b3;
                ldsm4t(b0, b1, b2, b3, bsAddr + (krow * 64 + col) * 4);
                #pragma unroll
                for (int mf = 0; mf < 2; mf++) {
                    mma_f16(acc[mf][2*nfp],   af[mf][0], af[mf][1], af[mf][2], af[mf][3], b0, b1);
                    mma_f16(acc[mf][2*nfp+1], af[mf][0], af[mf][1], af[mf][2], af[mf][3], b2, b3);
                }
            }
        }
    }

    if (mode == 0) {
        int gcol = col0 + warpN * 64;
        int isV = (gcol >= Dd + KVHh * HDd);
        int isK = (gcol >= Dd) && !isV;
        int headIdx;
        if (isV)      headIdx = (gcol - Dd - KVHh * HDd) >> 6;
        else if (isK) headIdx = (gcol - Dd) >> 6;
        else          headIdx = gcol >> 6;
        #pragma unroll
        for (int mf = 0; mf < 2; mf++) {
            #pragma unroll
            for (int half = 0; half < 2; half++) {
                int row = row0 + warpM * 32 + mf * 16 + lr + half * 8;
                int s_ = row & (Ss - 1), b_ = row >> 11;
                __half* dst;
                if (isV)
                    dst = g_v + ((size_t)(b_ * KVHh + headIdx) * Ss + s_) * HDd;
                else if (isK)
                    dst = g_k + ((size_t)(b_ * KVHh + headIdx) * Ss + s_) * HDd;
                else
                    dst = g_q + ((size_t)(b_ * Hh + headIdx) * Ss + s_) * HDd;
                const float* cosb = g_cos + ((size_t)b_ << 16) + (s_ << 5);
                const float* sinb = g_sin + ((size_t)b_ << 16) + (s_ << 5);
                #pragma unroll
                for (int nf = 0; nf < 4; nf++) {
                    int c0 = nf * 8 + 2 * lc;
                    float x1a = clip8(acc[mf][nf][half * 2 + 0]);
                    float x1b = clip8(acc[mf][nf][half * 2 + 1]);
                    float x2a = clip8(acc[mf][nf + 4][half * 2 + 0]);
                    float x2b = clip8(acc[mf][nf + 4][half * 2 + 1]);
                    if (isV) {
                        *(uint32_t*)(dst + c0)      = pkh2(x1a, x1b);
                        *(uint32_t*)(dst + c0 + 32) = pkh2(x2a, x2b);
                    } else {
                        float ca = cosb[c0], cb = cosb[c0 + 1];
                        float sa = sinb[c0], sb = sinb[c0 + 1];
                        *(uint32_t*)(dst + c0) =
                            pkh2(x1a * ca - x2a * sa, x1b * cb - x2b * sb);
                        *(uint32_t*)(dst + c0 + 32) =
                            pkh2(x2a * ca + x1a * sa, x2b * cb + x1b * sb);
                    }
                }
            }
        }
    } else {
        #pragma unroll
        for (int mf = 0; mf < 2; mf++) {
            #pragma unroll
            for (int half = 0; half < 2; half++) {
                int row = row0 + warpM * 32 + mf * 16 + lr + half * 8;
                #pragma unroll
                for (int nf = 0; nf < 8; nf++) {
                    int col = col0 + warpN * 64 + nf * 8 + 2 * lc;
                    size_t off = (size_t)row * N + col;
                    float2 rv = *(const float2*)(resid + off);
                    float2 v;
                    v.x = acc[mf][nf][half * 2 + 0] + rv.x;
                    v.y = acc[mf][nf][half * 2 + 1] + rv.y;
                    *(float2*)((float*)Cp + off) = v;
                }
            }
        }
    }
}

// ---------------- FP16 flash attention, 128-key macro-tiles, 3 stages ----------
#define KS_U 36
#define VS_U 32
#define NAS  3
#define KT_ROWS 128
#define SM_KS 0
#define SM_VS (NAS * KT_ROWS * KS_U)
#define SM_MASK (SM_VS + NAS * KT_ROWS * VS_U)
#define ATT_U32 (SM_MASK + NAS * KT_ROWS)
#define QP_U 36
#define NQT (Ss / 128)
__global__ __launch_bounds__(256, 2) void attn_kernel(const int* __restrict__ amask)
{
    extern __shared__ uint32_t smu[];
    uint32_t* Ps = smu;
    int* maskS = (int*)(smu + SM_MASK);

    int bid = blockIdx.x;
    int qt = (NQT - 1) - (bid >> 6);
    int rem = bid & 63;
    int h = rem >> 1;
    int b = rem & 1;
    int kvh = h >> 2;
    int q0 = qt * 128;
    int t = threadIdx.x;
    int w = t >> 5, l = t & 31;
    int lr = l >> 2, lc = l & 3;

    const uint4* Qg = (const uint4*)(g_q + ((size_t)(b * Hh + h) * Ss + q0) * HDd);
    const uint4* Kg = (const uint4*)(g_k + (size_t)(b * KVHh + kvh) * Ss * HDd);
    const uint4* Vg = (const uint4*)(g_v + (size_t)(b * KVHh + kvh) * Ss * HDd);
    const int*   Mg = amask + b * Ss;

    uint32_t smuBase = (uint32_t)__cvta_generic_to_shared(smu);

    #pragma unroll
    for (int i = 0; i < 4; i++) {
        int idx = i * 256 + t;
        int row = idx >> 3, c = idx & 7;
        *(uint4*)&Ps[row * QP_U + c * 4] = Qg[row * 8 + c];
    }
    __syncthreads();
    uint32_t qa[4][4];
    {
        int r0 = w * 16 + lr;
        #pragma unroll
        for (int ks = 0; ks < 4; ks++) {
            qa[ks][0] = Ps[r0 * QP_U + ks * 8 + lc];
            qa[ks][1] = Ps[(r0 + 8) * QP_U + ks * 8 + lc];
            qa[ks][2] = Ps[r0 * QP_U + ks * 8 + lc + 4];
            qa[ks][3] = Ps[(r0 + 8) * QP_U + ks * 8 + lc + 4];
        }
    }
    __syncthreads();

    int nkt = qt + 1;
    auto issueKV = [&](int kt, int stg) {
        if (kt < nkt) {
            int k0 = kt * KT_ROWS;
            uint32_t kBase = smuBase + (SM_KS + stg * KT_ROWS * KS_U) * 4;
            uint32_t vBase = smuBase + (SM_VS + stg * KT_ROWS * VS_U) * 4;
            #pragma unroll
            for (int i = 0; i < 4; i++) {
                int idx = i * 256 + t;
                int row = idx >> 3, c = idx & 7;
                cpa16(kBase + (row * KS_U + c * 4) * 4, Kg + (k0 + row) * 8 + c);
                cpa16(vBase + (row * VS_U + ((c * 4) ^ ((row & 7) << 2))) * 4,
                      Vg + (k0 + row) * 8 + c);
            }
            if (t < KT_ROWS)
                cpa4(smuBase + (SM_MASK + stg * KT_ROWS + t) * 4, Mg + k0 + t);
        }
        cpa_commit();
    };

    issueKV(0, 0);
    issueKV(1, 1);

    float m0 = -1e30f, m1 = -1e30f, l0 = 0.f, l1 = 0.f;
    float o[8][4];
    #pragma unroll
    for (int nf = 0; nf < 8; nf++)
        #pragma unroll
        for (int r = 0; r < 4; r++) o[nf][r] = 0.f;

    int kLdsmRow = l & 15;
    int kLdsmCol = (l >> 4) << 2;
    int qlow = q0 + w * 16;

    for (int kt = 0; kt < nkt; kt++) {
        cpa_wait<1>();
        __syncthreads();

        int cur = kt % NAS;
        uint32_t kbAddr = smuBase + (SM_KS + cur * KT_ROWS * KS_U) * 4;
        uint32_t vsAddr = smuBase + (SM_VS + cur * KT_ROWS * VS_U) * 4;

        #pragma unroll
        for (int half = 0; half < 2; half++) {
            if (half == 1) issueKV(kt + 2, (kt + 2) % NAS);

            int k0 = kt * KT_ROWS + half * 64;
            if (k0 <= qlow + 15) {
                int rbase = half * 64;
                float s[8][4];
                #pragma unroll
                for (int nf = 0; nf < 8; nf++)
                    #pragma unroll
                    for (int r = 0; r < 4; r++) s[nf][r] = 0.f;
                #pragma unroll
                for (int ks = 0; ks < 4; ks++) {
                    #pragma unroll
                    for (int p = 0; p < 4; p++) {
                        uint32_t b0, b1, b2, b3;
                        ldsm4(b0, b1, b2, b3,
                              kbAddr + ((rbase + p * 16 + kLdsmRow) * KS_U
                                        + ks * 8 + kLdsmCol) * 4);
                        mma_f16(s[2*p],   qa[ks][0], qa[ks][1], qa[ks][2], qa[ks][3], b0, b2);
                        mma_f16(s[2*p+1], qa[ks][0], qa[ks][1], qa[ks][2], qa[ks][3], b1, b3);
                    }
                }
                int qr0 = qlow + lr, qr1 = qr0 + 8;
                bool fullvis = (k0 + 63 <= qlow);
                int mbase = cur * KT_ROWS + rbase;
                #pragma unroll
                for (int nf = 0; nf < 8; nf++) {
                    int kg0 = k0 + nf * 8 + 2 * lc;
                    int ms0 = maskS[mbase + nf * 8 + 2 * lc];
                    int ms1 = maskS[mbase + nf * 8 + 2 * lc + 1];
                    s[nf][0] = (ms0 && (fullvis || kg0     <= qr0)) ? s[nf][0] * ATT_SCALE : -1e30f;
                    s[nf][1] = (ms1 && (fullvis || kg0 + 1 <= qr0)) ? s[nf][1] * ATT_SCALE : -1e30f;
                    s[nf][2] = (ms0 && (fullvis || kg0     <= qr1)) ? s[nf][2] * ATT_SCALE : -1e30f;
                    s[nf][3] = (ms1 && (fullvis || kg0 + 1 <= qr1)) ? s[nf][3] * ATT_SCALE : -1e30f;
                }
                float mt0 = -1e30f, mt1 = -1e30f;
                #pragma unroll
                for (int nf = 0; nf < 8; nf++) {
                    mt0 = fmaxf(mt0, fmaxf(s[nf][0], s[nf][1]));
                    mt1 = fmaxf(mt1, fmaxf(s[nf][2], s[nf][3]));
                }
                mt0 = fmaxf(mt0, __shfl_xor_sync(0xffffffffu, mt0, 1));
                mt0 = fmaxf(mt0, __shfl_xor_sync(0xffffffffu, mt0, 2));
                mt1 = fmaxf(mt1, __shfl_xor_sync(0xffffffffu, mt1, 1));
                mt1 = fmaxf(mt1, __shfl_xor_sync(0xffffffffu, mt1, 2));
                float mn0 = fmaxf(m0, mt0), mn1 = fmaxf(m1, mt1);
                float rs0 = 0.f, rs1 = 0.f;
                #pragma unroll
                for (int nf = 0; nf < 8; nf++) {
                    s[nf][0] = __expf(s[nf][0] - mn0);
                    s[nf][1] = __expf(s[nf][1] - mn0);
                    s[nf][2] = __expf(s[nf][2] - mn1);
                    s[nf][3] = __expf(s[nf][3] - mn1);
                    rs0 += s[nf][0] + s[nf][1];
                    rs1 += s[nf][2] + s[nf][3];
                }
                rs0 += __shfl_xor_sync(0xffffffffu, rs0, 1);
                rs0 += __shfl_xor_sync(0xffffffffu, rs0, 2);
                rs1 += __shfl_xor_sync(0xffffffffu, rs1, 1);
                rs1 += __shfl_xor_sync(0xffffffffu, rs1, 2);
                float a0 = __expf(m0 - mn0), a1 = __expf(m1 - mn1);
                l0 = l0 * a0 + rs0;  l1 = l1 * a1 + rs1;
                m0 = mn0;  m1 = mn1;
                #pragma unroll
                for (int nf = 0; nf < 8; nf++) {
                    o[nf][0] *= a0; o[nf][1] *= a0;
                    o[nf][2] *= a1; o[nf][3] *= a1;
                }
                #pragma unroll
                for (int ks = 0; ks < 4; ks++) {
                    uint32_t pa0 = pkh2(s[2*ks][0],   s[2*ks][1]);
                    uint32_t pa1 = pkh2(s[2*ks][2],   s[2*ks][3]);
                    uint32_t pa2 = pkh2(s[2*ks+1][0], s[2*ks+1][1]);
                    uint32_t pa3 = pkh2(s[2*ks+1][2], s[2*ks+1][3]);
                    #pragma unroll
                    for (int nfp = 0; nfp < 4; nfp++) {
                        int key = rbase + ks * 16 + (l & 15);
                        int col = nfp * 8 + ((l >> 4) << 2);
                        col ^= (key & 7) << 2;
                        uint32_t b0, b1, b2, b3;
                        ldsm4t(b0, b1, b2, b3, vsAddr + (key * VS_U + col) * 4);
                        mma_f16(o[2*nfp],   pa0, pa1, pa2, pa3, b0, b1);
                        mma_f16(o[2*nfp+1], pa0, pa1, pa2, pa3, b2, b3);
                    }
                }
            }
        }
    }

    float il0 = (l0 > 0.f) ? (1.f / l0) : 0.f;
    float il1 = (l1 > 0.f) ? (1.f / l1) : 0.f;
    int qr0 = q0 + w * 16 + lr;
    __half* d0 = g_attn + (size_t)(b * Ss + qr0) * Dd + h * HDd;
    __half* d1 = g_attn + (size_t)(b * Ss + qr0 + 8) * Dd + h * HDd;
    #pragma unroll
    for (int nf = 0; nf < 8; nf++) {
        int c = nf * 8 + 2 * lc;
        *(uint32_t*)(d0 + c) = pkh2(o[nf][0] * il0, o[nf][1] * il0);
        *(uint32_t*)(d1 + c) = pkh2(o[nf][2] * il1, o[nf][3] * il1);
    }
}

// ---------------- launch ------------------------------------------------------
extern "C" void kernel_launch(void* const* d_in, const int* in_sizes, int n_in,
                              void* d_out, int out_size)
{
    const float* hs   = (const float*)d_in[0];
    const int*   am   = (const int*)  d_in[1];
    const int*   pid  = (const int*)  d_in[2];
    const float* ln1  = (const float*)d_in[4];
    const float* wqkv = (const float*)d_in[5];
    const float* wout = (const float*)d_in[6];
    const float* ln2  = (const float*)d_in[7];
    float* out = (float*)d_out;

    __half *px, *pattn, *pwq, *pwo;
    cudaGetSymbolAddress((void**)&px,    g_x);
    cudaGetSymbolAddress((void**)&pattn, g_attn);
    cudaGetSymbolAddress((void**)&pwq,   g_wqkvh);
    cudaGetSymbolAddress((void**)&pwo,   g_wouth);

    const int ATTN_SMEM = ATT_U32 * 4;
    cudaFuncSetAttribute(attn_kernel,
                         cudaFuncAttributeMaxDynamicSharedMemorySize, ATTN_SMEM);
    const int GEMM_SMEM = NSTG * STAGE_U * 4;
    cudaFuncSetAttribute(gemm_f16_kernel,
                         cudaFuncAttributeMaxDynamicSharedMemorySize, GEMM_SMEM);

    prep_kernel<<<Mrows + 512 + NCVT, 256>>>(hs, ln1, pid, wqkv, wout);
    gemm_f16_kernel<<<(QKVN / BN) * (Mrows / BM), 256, GEMM_SMEM>>>(
        px, pwq, nullptr, Mrows, QKVN, Dd, 0, nullptr);
    attn_kernel<<<NQT * Hh * Bb, 256, ATTN_SMEM>>>(am);
    gemm_f16_kernel<<<(Dd / BN) * (Mrows / BM), 256, GEMM_SMEM>>>(
        pattn, pwo, out, Mrows, Dd, Dd, 1, hs);
    ln_kernel<<<Mrows, 256>>>(out, ln2, out + OUTOFF);
}